// round 5
// baseline (speedup 1.0000x reference)
#include <cuda_runtime.h>
#include <cuda_bf16.h>
#include <stdint.h>

#define NN 8192
#define FF 512
#define EPSF 1e-5f

// -------- scratch (static __device__ — no allocations allowed) --------
__device__ float g_rowsum[NN];
__device__ float g_colsum[NN];
__device__ __nv_bfloat16 g_Y[(size_t)NN * FF];   // Y = diag(r_inv) * X, bf16, row-major

// ============================ K0: zero accumulators ============================
__global__ void k0_zero(float* out) {
    int i = blockIdx.x * blockDim.x + threadIdx.x;
    if (i < NN) g_colsum[i] = 0.0f;
    if (i == 0) out[0] = 0.0f;
}

// ============================ K1: row + col sums of adj (one 256MB pass) ======
__global__ __launch_bounds__(256) void k1_sums(const float* __restrict__ adj) {
    __shared__ float scol[NN];   // 32 KB partial column sums
    __shared__ float srow[64];
    int tid = threadIdx.x;
    for (int c = tid; c < NN; c += 256) scol[c] = 0.0f;
    if (tid < 64) srow[tid] = 0.0f;
    __syncthreads();
    int r0 = blockIdx.x * 64;
    for (int rr = 0; rr < 64; ++rr) {
        const float* __restrict__ row = adj + (size_t)(r0 + rr) * NN;
        float rs = 0.0f;
#pragma unroll 8
        for (int c = tid; c < NN; c += 256) {
            float v = __ldg(row + c);
            rs += v;
            scol[c] += v;   // thread t owns cols == t (mod 256): conflict/race free
        }
#pragma unroll
        for (int o = 16; o; o >>= 1) rs += __shfl_down_sync(0xffffffffu, rs, o);
        if ((tid & 31) == 0) atomicAdd(&srow[rr], rs);
    }
    __syncthreads();
    if (tid < 64) g_rowsum[r0 + tid] = srow[tid];
    for (int c = tid; c < NN; c += 256) atomicAdd(&g_colsum[c], scol[c]);
}

// ============================ K2: r_inv, term1, Y=bf16(r*X) ====================
__global__ __launch_bounds__(256) void k2_prep(const float* __restrict__ X, float* out) {
    int wid = threadIdx.x >> 5, lane = threadIdx.x & 31;
    int row = blockIdx.x * 8 + wid;
    float d = 0.5f * (g_rowsum[row] + g_colsum[row]);   // degree of A=(adj+adjT)/2
    float rinv = rsqrtf(d + EPSF);
    const float4* __restrict__ x4 = (const float4*)(X + (size_t)row * FF);
    float s2 = 0.0f;
#pragma unroll
    for (int q = 0; q < 4; ++q) {
        float4 v = __ldg(x4 + q * 32 + lane);
        s2 += v.x * v.x + v.y * v.y + v.z * v.z + v.w * v.w;
        __nv_bfloat162* yp = (__nv_bfloat162*)(g_Y + (size_t)row * FF + (size_t)(q * 32 + lane) * 4);
        yp[0] = __floats2bfloat162_rn(v.x * rinv, v.y * rinv);
        yp[1] = __floats2bfloat162_rn(v.z * rinv, v.w * rinv);
    }
#pragma unroll
    for (int o = 16; o; o >>= 1) s2 += __shfl_down_sync(0xffffffffu, s2, o);
    if (lane == 0) atomicAdd(out, (d / (d + EPSF)) * s2);   // term1 contribution
}

// ============================ K3: S = sum adj .* (Y Y^T), mma.sync ============
// Base-ISA tensor path (tcgen05 not compilable under this harness's compute_103
// PTX target). 128 CTAs = 64 bi-blocks x 2 j-halves, 256 threads (8 warps, 2x4).
// Persistent A = Y[bi] 128x512 bf16 in SMEM (stride 520 bf16, ldmatrix
// conflict-free). B = Y[bj] streamed as 4 chunks of 128x64 bf16 via cp.async,
// double-buffered. Per warp: 64x32 output tile, m16n8k16 bf16 HMMA, 64 f32
// accums. Per-jt epilogue: adj float2 loads matching the accumulator fragment
// layout, FFMA reduce into one scalar, atomicAdd(-S) at the end.

#define A_STRIDE 520                     // bf16 elems per padded A row (1040 B)
#define B_STRIDE 72                      // bf16 elems per padded B row (144 B)
#define OFF_A    0u
#define OFF_B0   133120u                 // 128 * 1040
#define OFF_B1   (133120u + 18432u)      // + 128 * 144
#define OFF_RED  (133120u + 2u * 18432u) // 32 floats for block reduction
#define K3_SMEM  (OFF_RED + 128u)

__device__ __forceinline__ void cpasync16(uint32_t dst, const void* src) {
    asm volatile("cp.async.cg.shared.global [%0], [%1], 16;"
                 :: "r"(dst), "l"(src) : "memory");
}
__device__ __forceinline__ void cpcommit() {
    asm volatile("cp.async.commit_group;" ::: "memory");
}
__device__ __forceinline__ void cpwait0() {
    asm volatile("cp.async.wait_group 0;" ::: "memory");
}
__device__ __forceinline__ void ldmx4(uint32_t* r, uint32_t addr) {
    asm volatile("ldmatrix.sync.aligned.m8n8.x4.shared.b16 {%0,%1,%2,%3}, [%4];"
                 : "=r"(r[0]), "=r"(r[1]), "=r"(r[2]), "=r"(r[3]) : "r"(addr));
}
__device__ __forceinline__ void mma16816(float* c, const uint32_t* a,
                                         uint32_t b0, uint32_t b1) {
    asm volatile(
        "mma.sync.aligned.m16n8k16.row.col.f32.bf16.bf16.f32 "
        "{%0,%1,%2,%3}, {%4,%5,%6,%7}, {%8,%9}, {%0,%1,%2,%3};"
        : "+f"(c[0]), "+f"(c[1]), "+f"(c[2]), "+f"(c[3])
        : "r"(a[0]), "r"(a[1]), "r"(a[2]), "r"(a[3]), "r"(b0), "r"(b1));
}

__global__ void __launch_bounds__(256, 1) k3_gram(const float* __restrict__ adj,
                                                  float* out) {
    extern __shared__ char smc[];
    uint32_t sb = (uint32_t)__cvta_generic_to_shared(smc);

    const int tid = threadIdx.x, lane = tid & 31, wid = tid >> 5;
    const int wm = wid >> 2;                  // 0..1 : 64-row slice
    const int wn = wid & 3;                   // 0..3 : 32-col slice
    const int bi = blockIdx.x >> 1;
    const int j0 = (blockIdx.x & 1) * 32;

    // ---- kick off persistent A tile: Y[bi] 128x512 (8192 x 16B segs) ----
    {
        const char* srcbase = (const char*)(g_Y + (size_t)bi * 128 * FF);
#pragma unroll
        for (int u = 0; u < 32; ++u) {
            int g = tid + 256 * u;
            int r = g >> 6, s = g & 63;       // 64 segs per row
            cpasync16(sb + OFF_A + (uint32_t)(r * 1040 + s * 16),
                      srcbase + (size_t)r * 1024 + s * 16);
        }
        cpcommit();
    }
    // ---- kick off B chunk 0 ----
    {
        int bj = j0;                          // jt = 0, c = 0
        const char* srcbase = (const char*)(g_Y + (size_t)bj * 128 * FF);
#pragma unroll
        for (int u = 0; u < 4; ++u) {
            int g = tid + 256 * u;            // 1024 segs: 128 rows x 8 segs
            int r = g >> 3, s = g & 7;
            cpasync16(sb + OFF_B0 + (uint32_t)(r * 144 + s * 16),
                      srcbase + (size_t)r * 1024 + s * 16);
        }
        cpcommit();
    }

    // per-thread ldmatrix base addresses (lane%16 = row-within-16, lane/16 = 16B col)
    const uint32_t aBase = sb + OFF_A
        + (uint32_t)((wm * 64 + (lane & 15)) * 1040 + (lane >> 4) * 16);
    const uint32_t bRowOff =
        (uint32_t)((wn * 32 + (lane & 15)) * 144 + (lane >> 4) * 16);

    float acc[4][4][4];
#pragma unroll
    for (int mt = 0; mt < 4; ++mt)
#pragma unroll
        for (int nt = 0; nt < 4; ++nt)
#pragma unroll
            for (int q = 0; q < 4; ++q) acc[mt][nt][q] = 0.0f;

    float sacc = 0.0f;
    const int g_row = lane >> 2;              // 0..7  fragment row within 8
    const int g_tg  = lane & 3;               // fragment col pair index

    for (int g = 0; g < 128; ++g) {           // 32 jt x 4 chunks
        cpwait0();                            // chunk g (and A on g==0) complete
        __syncthreads();                      // visibility + prev compute done
        if (g + 1 < 128) {                    // prefetch next chunk into other buf
            int jn = (g + 1) >> 2, cn = (g + 1) & 3;
            int bj = j0 + jn;
            uint32_t bb = ((g + 1) & 1) ? OFF_B1 : OFF_B0;
            const char* srcbase =
                (const char*)(g_Y + (size_t)bj * 128 * FF) + cn * 128;
#pragma unroll
            for (int u = 0; u < 4; ++u) {
                int q = tid + 256 * u;
                int r = q >> 3, s = q & 7;
                cpasync16(sb + bb + (uint32_t)(r * 144 + s * 16),
                          srcbase + (size_t)r * 1024 + s * 16);
            }
        }
        cpcommit();                           // (empty group ok on last iter)

        // ---- compute chunk g: K cols [c*64, +64) ----
        const int c = g & 3;
        const uint32_t bBufBase = sb + ((g & 1) ? OFF_B1 : OFF_B0) + bRowOff;
        const uint32_t aChunk = aBase + (uint32_t)(c * 128);
#pragma unroll
        for (int ks = 0; ks < 4; ++ks) {
            uint32_t afr[4][4], bfr[2][4];
#pragma unroll
            for (int mt = 0; mt < 4; ++mt)
                ldmx4(afr[mt], aChunk + (uint32_t)(mt * 16 * 1040 + ks * 32));
#pragma unroll
            for (int bt = 0; bt < 2; ++bt)
                ldmx4(bfr[bt], bBufBase + (uint32_t)(bt * 16 * 144 + ks * 32));
#pragma unroll
            for (int mt = 0; mt < 4; ++mt)
#pragma unroll
                for (int nt = 0; nt < 4; ++nt) {
                    const uint32_t* bf = bfr[nt >> 1];
                    if (nt & 1) mma16816(acc[mt][nt], afr[mt], bf[1], bf[3]);
                    else        mma16816(acc[mt][nt], afr[mt], bf[0], bf[2]);
                }
        }

        // ---- per-jt epilogue: fold adj tile into scalar, reset accums ----
        if ((g & 3) == 3) {
            int bj = j0 + (g >> 2);
            const float* __restrict__ abase =
                adj + (size_t)(bi * 128 + wm * 64 + g_row) * NN
                    + (size_t)(bj * 128 + wn * 32 + g_tg * 2);
#pragma unroll
            for (int mt = 0; mt < 4; ++mt) {
                const float* r0 = abase + (size_t)(mt * 16) * NN;
                const float* r1 = r0 + (size_t)8 * NN;
#pragma unroll
                for (int nt = 0; nt < 4; ++nt) {
                    float2 p0 = __ldg((const float2*)(r0 + nt * 8));
                    float2 p1 = __ldg((const float2*)(r1 + nt * 8));
                    float* a = acc[mt][nt];
                    sacc += p0.x * a[0] + p0.y * a[1] + p1.x * a[2] + p1.y * a[3];
                    a[0] = a[1] = a[2] = a[3] = 0.0f;
                }
            }
        }
    }

    // ---- block reduce, subtract S ----
#pragma unroll
    for (int o = 16; o; o >>= 1) sacc += __shfl_down_sync(0xffffffffu, sacc, o);
    float* wacc = (float*)(smc + OFF_RED);
    __syncthreads();
    if (lane == 0) wacc[wid] = sacc;
    __syncthreads();
    if (tid == 0) {
        float s = 0.0f;
#pragma unroll
        for (int w = 0; w < 8; ++w) s += wacc[w];
        atomicAdd(out, -s);
    }
}

// ============================ launch ============================
extern "C" void kernel_launch(void* const* d_in, const int* in_sizes, int n_in,
                              void* d_out, int out_size) {
    const float* adj = (const float*)d_in[0];
    const float* X   = (const float*)d_in[1];
    float* out = (float*)d_out;

    cudaFuncSetAttribute(k3_gram, cudaFuncAttributeMaxDynamicSharedMemorySize,
                         K3_SMEM);

    k0_zero<<<32, 256>>>(out);
    k1_sums<<<128, 256>>>(adj);
    k2_prep<<<1024, 256>>>(X, out);
    k3_gram<<<128, 256, K3_SMEM>>>(adj, out);
}

// round 6
// speedup vs baseline: 1.3016x; 1.3016x over previous
#include <cuda_runtime.h>
#include <cuda_bf16.h>
#include <stdint.h>

#define NN 8192
#define FF 512
#define EPSF 1e-5f

// -------- scratch (static __device__ — no allocations allowed) --------
__device__ float g_rowsum[NN];
__device__ float g_colsum[NN];
__device__ __nv_bfloat16 g_Y[(size_t)NN * FF];   // Y = diag(r_inv) * X, bf16, row-major

// ============================ K0: zero accumulators ============================
__global__ void k0_zero(float* out) {
    int i = blockIdx.x * blockDim.x + threadIdx.x;
    if (i < NN) g_colsum[i] = 0.0f;
    if (i == 0) out[0] = 0.0f;
}

// ============================ K1: row + col sums of adj =======================
// Register-resident column accumulators (no smem RMW chains), float4 loads,
// 148 balanced CTAs. Column sums finalized with spread atomics.
__global__ __launch_bounds__(256) void k1_sums(const float* __restrict__ adj) {
    __shared__ float srow[64];
    int tid = threadIdx.x, lane = tid & 31;
    int r0 = (int)(((long long)blockIdx.x * NN) / 148);
    int r1 = (int)(((long long)(blockIdx.x + 1) * NN) / 148);
    for (int i = tid; i < 64; i += 256) srow[i] = 0.0f;
    __syncthreads();

    float4 ca[8];
#pragma unroll
    for (int j = 0; j < 8; ++j) ca[j] = make_float4(0.f, 0.f, 0.f, 0.f);

    for (int r = r0; r < r1; ++r) {
        const float4* __restrict__ row = (const float4*)(adj + (size_t)r * NN);
        float rp = 0.0f;
#pragma unroll
        for (int j = 0; j < 8; ++j) {
            float4 v = __ldg(row + tid + 256 * j);
            ca[j].x += v.x; ca[j].y += v.y; ca[j].z += v.z; ca[j].w += v.w;
            rp += (v.x + v.y) + (v.z + v.w);
        }
#pragma unroll
        for (int o = 16; o; o >>= 1) rp += __shfl_down_sync(0xffffffffu, rp, o);
        if (lane == 0) atomicAdd(&srow[r - r0], rp);
    }
    __syncthreads();
    for (int i = tid; i < r1 - r0; i += 256) g_rowsum[r0 + i] = srow[i];
#pragma unroll
    for (int j = 0; j < 8; ++j) {
        int c = (tid + 256 * j) * 4;
        atomicAdd(&g_colsum[c + 0], ca[j].x);
        atomicAdd(&g_colsum[c + 1], ca[j].y);
        atomicAdd(&g_colsum[c + 2], ca[j].z);
        atomicAdd(&g_colsum[c + 3], ca[j].w);
    }
}

// ============================ K2: r_inv, term1, Y=bf16(r*X) ====================
__global__ __launch_bounds__(256) void k2_prep(const float* __restrict__ X, float* out) {
    int wid = threadIdx.x >> 5, lane = threadIdx.x & 31;
    int row = blockIdx.x * 8 + wid;
    float d = 0.5f * (g_rowsum[row] + g_colsum[row]);   // degree of A=(adj+adjT)/2
    float rinv = rsqrtf(d + EPSF);
    const float4* __restrict__ x4 = (const float4*)(X + (size_t)row * FF);
    float s2 = 0.0f;
#pragma unroll
    for (int q = 0; q < 4; ++q) {
        float4 v = __ldg(x4 + q * 32 + lane);
        s2 += v.x * v.x + v.y * v.y + v.z * v.z + v.w * v.w;
        __nv_bfloat162* yp = (__nv_bfloat162*)(g_Y + (size_t)row * FF + (size_t)(q * 32 + lane) * 4);
        yp[0] = __floats2bfloat162_rn(v.x * rinv, v.y * rinv);
        yp[1] = __floats2bfloat162_rn(v.z * rinv, v.w * rinv);
    }
#pragma unroll
    for (int o = 16; o; o >>= 1) s2 += __shfl_down_sync(0xffffffffu, s2, o);
    if (lane == 0) atomicAdd(out, (d / (d + EPSF)) * s2);   // term1 contribution
}

// ============================ K3: S = sum adj .* (Y Y^T), triangular ==========
// G = Y Y^T is symmetric: compute each 128x128 tile (bi<=bj) ONCE (2080 tiles),
// weight with adj(I,J) + adj(J,I)^T (diag tiles weight adj(I,I) alone).
// 148 CTAs x 512 threads (16 warps, 4x4 grid of 32x32 warp tiles). Per tile:
// 4 K-chunks of 128 cols; A=Y[bi] and B=Y[bj] chunk tiles (128x128 bf16 each)
// cp.async double-buffered. m16n8k16 bf16 HMMA, FULL K=512.

#define BSTR   272                       // bytes per buffered row (128 bf16 + pad)
#define SZBUF  (128 * BSTR)              // 34816
#define OFF_A0 0u
#define OFF_A1 34816u
#define OFF_Bu0 69632u
#define OFF_Bu1 104448u
#define OFF_RED 139264u
#define K3_SMEM (139264u + 128u)

__device__ __forceinline__ void cpasync16(uint32_t dst, const void* src) {
    asm volatile("cp.async.cg.shared.global [%0], [%1], 16;"
                 :: "r"(dst), "l"(src) : "memory");
}
__device__ __forceinline__ void cpcommit() {
    asm volatile("cp.async.commit_group;" ::: "memory");
}
__device__ __forceinline__ void cpwait0() {
    asm volatile("cp.async.wait_group 0;" ::: "memory");
}
__device__ __forceinline__ void ldmx4(uint32_t* r, uint32_t addr) {
    asm volatile("ldmatrix.sync.aligned.m8n8.x4.shared.b16 {%0,%1,%2,%3}, [%4];"
                 : "=r"(r[0]), "=r"(r[1]), "=r"(r[2]), "=r"(r[3]) : "r"(addr));
}
__device__ __forceinline__ void mma16816(float* c, const uint32_t* a,
                                         uint32_t b0, uint32_t b1) {
    asm volatile(
        "mma.sync.aligned.m16n8k16.row.col.f32.bf16.bf16.f32 "
        "{%0,%1,%2,%3}, {%4,%5,%6,%7}, {%8,%9}, {%0,%1,%2,%3};"
        : "+f"(c[0]), "+f"(c[1]), "+f"(c[2]), "+f"(c[3])
        : "r"(a[0]), "r"(a[1]), "r"(a[2]), "r"(a[3]), "r"(b0), "r"(b1));
}

__device__ __forceinline__ void load_chunk(uint32_t sb, int buf, int bi, int bj,
                                           int c, int tid) {
    const char* asrc = (const char*)(g_Y + (size_t)bi * 128 * FF) + c * 256;
    const char* bsrc = (const char*)(g_Y + (size_t)bj * 128 * FF) + c * 256;
    uint32_t ab = sb + (buf ? OFF_A1 : OFF_A0);
    uint32_t bb = sb + (buf ? OFF_Bu1 : OFF_Bu0);
#pragma unroll
    for (int u = 0; u < 4; ++u) {
        int g2 = tid + 512 * u;              // 2048 segs: 128 rows x 16 x 16B
        int r = g2 >> 4, s = g2 & 15;
        cpasync16(ab + (uint32_t)(r * BSTR + s * 16),
                  asrc + (size_t)r * 1024 + s * 16);
        cpasync16(bb + (uint32_t)(r * BSTR + s * 16),
                  bsrc + (size_t)r * 1024 + s * 16);
    }
}

__global__ void __launch_bounds__(512, 1) k3_tri(const float* __restrict__ adj,
                                                 float* out) {
    extern __shared__ char smc[];
    uint32_t sb = (uint32_t)__cvta_generic_to_shared(smc);
    const int tid = threadIdx.x, lane = tid & 31, wid = tid >> 5;
    const int wm = wid >> 2, wn = wid & 3;   // 4x4 warp grid, 32x32 tiles

    int t0 = (int)(((long long)blockIdx.x * 2080) / 148);
    int t1 = (int)(((long long)(blockIdx.x + 1) * 2080) / 148);

    int bi = 0, rem = t0;
    while (rem >= 64 - bi) { rem -= 64 - bi; ++bi; }
    int bj = bi + rem;

    load_chunk(sb, 0, bi, bj, 0, tid);
    cpcommit();

    const uint32_t aoff = (uint32_t)((wm * 32 + (lane & 15)) * BSTR + (lane >> 4) * 16);
    const uint32_t boff = (uint32_t)((wn * 32 + (lane & 15)) * BSTR + (lane >> 4) * 16);

    float acc[2][4][4];
#pragma unroll
    for (int mt = 0; mt < 2; ++mt)
#pragma unroll
        for (int nt = 0; nt < 4; ++nt)
#pragma unroll
            for (int e = 0; e < 4; ++e) acc[mt][nt][e] = 0.0f;
    float sacc = 0.0f;

    int q = 0;
    for (int t = t0; t < t1; ++t) {
        int bin = bi, bjn = bj + 1;          // next tile (row-major triangle)
        if (bjn >= 64) { bin = bi + 1; bjn = bin; }

        for (int c = 0; c < 4; ++c, ++q) {
            cpwait0();
            __syncthreads();                 // chunk q visible; chunk q-1 consumed
            bool more = (c < 3) || (t + 1 < t1);
            if (more) {
                int nbi = (c < 3) ? bi : bin;
                int nbj = (c < 3) ? bj : bjn;
                int nc  = (c < 3) ? c + 1 : 0;
                load_chunk(sb, (q + 1) & 1, nbi, nbj, nc, tid);
            }
            cpcommit();

            uint32_t ab = sb + ((q & 1) ? OFF_A1 : OFF_A0) + aoff;
            uint32_t bb = sb + ((q & 1) ? OFF_Bu1 : OFF_Bu0) + boff;
#pragma unroll
            for (int ks = 0; ks < 8; ++ks) {
                uint32_t afr[2][4], bfr[2][4];
                ldmx4(afr[0], ab + ks * 32);
                ldmx4(afr[1], ab + 16 * BSTR + ks * 32);
                ldmx4(bfr[0], bb + ks * 32);
                ldmx4(bfr[1], bb + 16 * BSTR + ks * 32);
#pragma unroll
                for (int mt = 0; mt < 2; ++mt)
#pragma unroll
                    for (int nt = 0; nt < 4; ++nt) {
                        const uint32_t* bf = bfr[nt >> 1];
                        uint32_t b0 = (nt & 1) ? bf[1] : bf[0];
                        uint32_t b1 = (nt & 1) ? bf[3] : bf[2];
                        mma16816(acc[mt][nt], afr[mt], b0, b1);
                    }
            }
        }

        // ---- epilogue: weight = adj(I,J) (+ adj(J,I)^T if off-diagonal) ----
        {
            const bool offd = (bi != bj);
            const int rb = bi * 128 + wm * 32 + (lane >> 2);
            const int cb = bj * 128 + wn * 32 + (lane & 3) * 2;
#pragma unroll
            for (int mt = 0; mt < 2; ++mt)
#pragma unroll
                for (int h = 0; h < 2; ++h) {
                    int r = rb + mt * 16 + h * 8;
                    const float* __restrict__ rowp = adj + (size_t)r * NN + cb;
#pragma unroll
                    for (int nt = 0; nt < 4; ++nt) {
                        float2 d = __ldg((const float2*)(rowp + nt * 8));
                        float w0 = d.x, w1 = d.y;
                        if (offd) {
                            int cc = cb + nt * 8;
                            w0 += __ldg(adj + (size_t)cc * NN + r);
                            w1 += __ldg(adj + (size_t)(cc + 1) * NN + r);
                        }
                        float* a = acc[mt][nt];
                        sacc += w0 * a[h * 2 + 0] + w1 * a[h * 2 + 1];
                    }
                }
#pragma unroll
            for (int mt = 0; mt < 2; ++mt)
#pragma unroll
                for (int nt = 0; nt < 4; ++nt)
#pragma unroll
                    for (int e = 0; e < 4; ++e) acc[mt][nt][e] = 0.0f;
        }
        bi = bin; bj = bjn;
    }

    // ---- block reduce, subtract S ----
#pragma unroll
    for (int o = 16; o; o >>= 1) sacc += __shfl_down_sync(0xffffffffu, sacc, o);
    float* wacc = (float*)(smc + OFF_RED);
    __syncthreads();
    if (lane == 0) wacc[wid] = sacc;
    __syncthreads();
    if (tid == 0) {
        float s = 0.0f;
#pragma unroll
        for (int w = 0; w < 16; ++w) s += wacc[w];
        atomicAdd(out, -s);
    }
}

// ============================ launch ============================
extern "C" void kernel_launch(void* const* d_in, const int* in_sizes, int n_in,
                              void* d_out, int out_size) {
    const float* adj = (const float*)d_in[0];
    const float* X   = (const float*)d_in[1];
    float* out = (float*)d_out;

    cudaFuncSetAttribute(k3_tri, cudaFuncAttributeMaxDynamicSharedMemorySize,
                         K3_SMEM);

    k0_zero<<<32, 256>>>(out);
    k1_sums<<<148, 256>>>(adj);
    k2_prep<<<1024, 256>>>(X, out);
    k3_tri<<<148, 512, K3_SMEM>>>(adj, out);
}

// round 11
// speedup vs baseline: 1.3923x; 1.0697x over previous
#include <cuda_runtime.h>
#include <cuda_bf16.h>
#include <stdint.h>

#define NN 8192
#define FF 512
#define EPSF 1e-5f

// -------- scratch (static __device__ — no allocations allowed) --------
__device__ float g_rowsum[NN];
__device__ float g_colsum[NN];
__device__ __nv_bfloat16 g_Y[(size_t)NN * FF];   // Y = diag(r_inv) * X, bf16, row-major

// ============================ K0: zero accumulators ============================
__global__ void k0_zero(float* out) {
    int i = blockIdx.x * blockDim.x + threadIdx.x;
    if (i < NN) g_colsum[i] = 0.0f;
    if (i == 0) out[0] = 0.0f;
}

// ============================ K1: row + col sums of adj (R6 version) ==========
// 148 balanced CTAs; 256 threads span the FULL row (tid + 256j, j<8 -> all 2048
// float4). Register col-accumulators; rowsum via shuffle + smem atomic.
__global__ __launch_bounds__(256) void k1_sums(const float* __restrict__ adj) {
    __shared__ float srow[64];
    int tid = threadIdx.x, lane = tid & 31;
    int r0 = (int)(((long long)blockIdx.x * NN) / 148);
    int r1 = (int)(((long long)(blockIdx.x + 1) * NN) / 148);
    for (int i = tid; i < 64; i += 256) srow[i] = 0.0f;
    __syncthreads();

    float4 ca[8];
#pragma unroll
    for (int j = 0; j < 8; ++j) ca[j] = make_float4(0.f, 0.f, 0.f, 0.f);

    for (int r = r0; r < r1; ++r) {
        const float4* __restrict__ row = (const float4*)(adj + (size_t)r * NN);
        float rp = 0.0f;
#pragma unroll
        for (int j = 0; j < 8; ++j) {
            float4 v = __ldg(row + tid + 256 * j);
            ca[j].x += v.x; ca[j].y += v.y; ca[j].z += v.z; ca[j].w += v.w;
            rp += (v.x + v.y) + (v.z + v.w);
        }
#pragma unroll
        for (int o = 16; o; o >>= 1) rp += __shfl_down_sync(0xffffffffu, rp, o);
        if (lane == 0) atomicAdd(&srow[r - r0], rp);
    }
    __syncthreads();
    for (int i = tid; i < r1 - r0; i += 256) g_rowsum[r0 + i] = srow[i];
#pragma unroll
    for (int j = 0; j < 8; ++j) {
        int c = (tid + 256 * j) * 4;
        atomicAdd(&g_colsum[c + 0], ca[j].x);
        atomicAdd(&g_colsum[c + 1], ca[j].y);
        atomicAdd(&g_colsum[c + 2], ca[j].z);
        atomicAdd(&g_colsum[c + 3], ca[j].w);
    }
}

// ============================ K2: r_inv, term1, Y=bf16(r*X) ====================
// Block-reduced term1: ONE atomicAdd per CTA (same-address L2 atomics serialize).
__global__ __launch_bounds__(256) void k2_prep(const float* __restrict__ X, float* out) {
    __shared__ float sterm[8];
    int wid = threadIdx.x >> 5, lane = threadIdx.x & 31;
    int row = blockIdx.x * 8 + wid;
    float d = 0.5f * (g_rowsum[row] + g_colsum[row]);   // degree of A=(adj+adjT)/2
    float rinv = rsqrtf(d + EPSF);
    const float4* __restrict__ x4 = (const float4*)(X + (size_t)row * FF);
    float s2 = 0.0f;
#pragma unroll
    for (int q = 0; q < 4; ++q) {
        float4 v = __ldg(x4 + q * 32 + lane);
        s2 += v.x * v.x + v.y * v.y + v.z * v.z + v.w * v.w;
        __nv_bfloat162* yp = (__nv_bfloat162*)(g_Y + (size_t)row * FF + (size_t)(q * 32 + lane) * 4);
        yp[0] = __floats2bfloat162_rn(v.x * rinv, v.y * rinv);
        yp[1] = __floats2bfloat162_rn(v.z * rinv, v.w * rinv);
    }
#pragma unroll
    for (int o = 16; o; o >>= 1) s2 += __shfl_down_sync(0xffffffffu, s2, o);
    if (lane == 0) sterm[wid] = (d / (d + EPSF)) * s2;
    __syncthreads();
    if (threadIdx.x == 0) {
        float t = 0.0f;
#pragma unroll
        for (int w = 0; w < 8; ++w) t += sterm[w];
        atomicAdd(out, t);
    }
}

// ============================ K3: S = sum adj .* (Y Y^T), triangular ==========
// 148 CTAs x 512 threads, 16 warps (4x4 of 32x32), 128x128 tiles over the upper
// triangle (2080 tiles). K split into 8 chunks of 64; A/B chunk tiles double-
// buffered via cp.async. adj(I,J) and adj(J,I) STAGED into SMEM via cp.async in
// 7 pieces riding the Y-chunk commit groups of chunks 0..6 (complete by chunk-7
// wait) -> epilogue is pure LDS + FFMA, no scattered LDGs, adj DRAM overlapped.

#define BSTR    144                      // bytes per Y-buffer row (64 bf16 + pad)
#define SROW    528                      // bytes per staged adj row (128 f32 + pad)
#define OFF_A0  0u
#define OFF_A1  18432u
#define OFF_B0  36864u
#define OFF_B1  55296u
#define OFF_S1  73728u
#define OFF_S2  141312u                  // 73728 + 128*528
#define OFF_RED 208896u                  // 141312 + 128*528
#define K3_SMEM (208896u + 128u)

__device__ __forceinline__ void cpasync16(uint32_t dst, const void* src) {
    asm volatile("cp.async.cg.shared.global [%0], [%1], 16;"
                 :: "r"(dst), "l"(src) : "memory");
}
__device__ __forceinline__ void cpcommit() {
    asm volatile("cp.async.commit_group;" ::: "memory");
}
__device__ __forceinline__ void cpwait0() {
    asm volatile("cp.async.wait_group 0;" ::: "memory");
}
__device__ __forceinline__ void ldmx4(uint32_t* r, uint32_t addr) {
    asm volatile("ldmatrix.sync.aligned.m8n8.x4.shared.b16 {%0,%1,%2,%3}, [%4];"
                 : "=r"(r[0]), "=r"(r[1]), "=r"(r[2]), "=r"(r[3]) : "r"(addr));
}
__device__ __forceinline__ void mma16816(float* c, const uint32_t* a,
                                         uint32_t b0, uint32_t b1) {
    asm volatile(
        "mma.sync.aligned.m16n8k16.row.col.f32.bf16.bf16.f32 "
        "{%0,%1,%2,%3}, {%4,%5,%6,%7}, {%8,%9}, {%0,%1,%2,%3};"
        : "+f"(c[0]), "+f"(c[1]), "+f"(c[2]), "+f"(c[3])
        : "r"(a[0]), "r"(a[1]), "r"(a[2]), "r"(a[3]), "r"(b0), "r"(b1));
}

// Y chunk: rows 128, K cols [c*64, +64) of Y[bi] -> buf A, Y[bj] -> buf B.
__device__ __forceinline__ void load_chunk(uint32_t sb, int buf, int bi, int bj,
                                           int c, int tid) {
    const char* asrc = (const char*)(g_Y + (size_t)bi * 128 * FF) + c * 128;
    const char* bsrc = (const char*)(g_Y + (size_t)bj * 128 * FF) + c * 128;
    uint32_t ab = sb + (buf ? OFF_A1 : OFF_A0);
    uint32_t bb = sb + (buf ? OFF_B1 : OFF_B0);
#pragma unroll
    for (int u = 0; u < 2; ++u) {
        int g2 = tid + 512 * u;              // 1024 segs: 128 rows x 8 x 16B
        int r = g2 >> 3, s = g2 & 7;
        cpasync16(ab + (uint32_t)(r * BSTR + s * 16),
                  asrc + (size_t)r * 1024 + s * 16);
        cpasync16(bb + (uint32_t)(r * BSTR + s * 16),
                  bsrc + (size_t)r * 1024 + s * 16);
    }
}

// adj staging piece p (0..6): rows [R*p/7, R*(p+1)/7) of the combined S1(+S2) set.
__device__ __forceinline__ void load_adj_piece(uint32_t sb, const float* adj,
                                               int bi, int bj, int R, int p,
                                               int tid) {
    int rlo = (R * p) / 7, rhi = (R * (p + 1)) / 7;
    int nseg = (rhi - rlo) * 32;             // 32 x 16B per 512B row
    const char* b1 = (const char*)(adj + (size_t)(bi * 128) * NN + bj * 128);
    const char* b2 = (const char*)(adj + (size_t)(bj * 128) * NN + bi * 128);
    for (int s2 = tid; s2 < nseg; s2 += 512) {
        int rr = rlo + (s2 >> 5), sg = s2 & 31;
        if (rr < 128)
            cpasync16(sb + OFF_S1 + (uint32_t)(rr * SROW + sg * 16),
                      b1 + (size_t)rr * (NN * 4) + sg * 16);
        else
            cpasync16(sb + OFF_S2 + (uint32_t)((rr - 128) * SROW + sg * 16),
                      b2 + (size_t)(rr - 128) * (NN * 4) + sg * 16);
    }
}

__global__ void __launch_bounds__(512, 1) k3_tri(const float* __restrict__ adj,
                                                 float* out) {
    extern __shared__ char smc[];
    uint32_t sb = (uint32_t)__cvta_generic_to_shared(smc);
    const int tid = threadIdx.x, lane = tid & 31, wid = tid >> 5;
    const int wm = wid >> 2, wn = wid & 3;   // 4x4 warp grid, 32x32 tiles

    int t0 = (int)(((long long)blockIdx.x * 2080) / 148);
    int t1 = (int)(((long long)(blockIdx.x + 1) * 2080) / 148);

    int bi = 0, rem = t0;
    while (rem >= 64 - bi) { rem -= 64 - bi; ++bi; }
    int bj = bi + rem;

    load_chunk(sb, 0, bi, bj, 0, tid);
    cpcommit();

    const uint32_t aoff = (uint32_t)((wm * 32 + (lane & 15)) * BSTR + (lane >> 4) * 16);
    const uint32_t boff = (uint32_t)((wn * 32 + (lane & 15)) * BSTR + (lane >> 4) * 16);

    float acc[2][4][4];
#pragma unroll
    for (int mt = 0; mt < 2; ++mt)
#pragma unroll
        for (int nt = 0; nt < 4; ++nt)
#pragma unroll
            for (int e = 0; e < 4; ++e) acc[mt][nt][e] = 0.0f;
    float sacc = 0.0f;

    int q = 0;
    for (int t = t0; t < t1; ++t) {
        int bin = bi, bjn = bj + 1;          // next tile (row-major triangle)
        if (bjn >= 64) { bin = bi + 1; bjn = bin; }
        const bool offd = (bi != bj);
        const int R = offd ? 256 : 128;

        for (int c = 0; c < 8; ++c, ++q) {
            cpwait0();
            __syncthreads();                 // chunk q visible; prev consumed
            bool more = (c < 7) || (t + 1 < t1);
            if (more) {
                int nbi = (c < 7) ? bi : bin;
                int nbj = (c < 7) ? bj : bjn;
                int nc  = (c < 7) ? c + 1 : 0;
                load_chunk(sb, (q + 1) & 1, nbi, nbj, nc, tid);
            }
            if (c < 7) load_adj_piece(sb, adj, bi, bj, R, c, tid);
            cpcommit();

            uint32_t ab = sb + ((q & 1) ? OFF_A1 : OFF_A0) + aoff;
            uint32_t bb = sb + ((q & 1) ? OFF_B1 : OFF_B0) + boff;
#pragma unroll
            for (int ks = 0; ks < 4; ++ks) {
                uint32_t afr[2][4], bfr[2][4];
                ldmx4(afr[0], ab + ks * 32);
                ldmx4(afr[1], ab + 16 * BSTR + ks * 32);
                ldmx4(bfr[0], bb + ks * 32);
                ldmx4(bfr[1], bb + 16 * BSTR + ks * 32);
#pragma unroll
                for (int mt = 0; mt < 2; ++mt)
#pragma unroll
                    for (int nt = 0; nt < 4; ++nt) {
                        const uint32_t* bf = bfr[nt >> 1];
                        uint32_t b0 = (nt & 1) ? bf[1] : bf[0];
                        uint32_t b1 = (nt & 1) ? bf[3] : bf[2];
                        mma16816(acc[mt][nt], afr[mt], b0, b1);
                    }
            }
        }

        // ---- epilogue from SMEM: w = S1[r][c] (+ S2[c][r] if off-diagonal) ----
        {
            const int rb = wm * 32 + (lane >> 2);
            const int cb = wn * 32 + (lane & 3) * 2;
#pragma unroll
            for (int mt = 0; mt < 2; ++mt)
#pragma unroll
                for (int h = 0; h < 2; ++h) {
                    int r = rb + mt * 16 + h * 8;
                    const char* s1row = smc + OFF_S1 + r * SROW;
#pragma unroll
                    for (int nt = 0; nt < 4; ++nt) {
                        int cc = cb + nt * 8;
                        float2 d = *(const float2*)(s1row + cc * 4);
                        float w0 = d.x, w1 = d.y;
                        if (offd) {
                            w0 += *(const float*)(smc + OFF_S2 + cc * SROW + r * 4);
                            w1 += *(const float*)(smc + OFF_S2 + (cc + 1) * SROW + r * 4);
                        }
                        float* a = acc[mt][nt];
                        sacc += w0 * a[h * 2 + 0] + w1 * a[h * 2 + 1];
                    }
                }
#pragma unroll
            for (int mt = 0; mt < 2; ++mt)
#pragma unroll
                for (int nt = 0; nt < 4; ++nt)
#pragma unroll
                    for (int e = 0; e < 4; ++e) acc[mt][nt][e] = 0.0f;
        }
        bi = bin; bj = bjn;
    }

    // ---- block reduce, subtract S ----
#pragma unroll
    for (int o = 16; o; o >>= 1) sacc += __shfl_down_sync(0xffffffffu, sacc, o);
    float* wacc = (float*)(smc + OFF_RED);
    __syncthreads();
    if (lane == 0) wacc[wid] = sacc;
    __syncthreads();
    if (tid == 0) {
        float s = 0.0f;
#pragma unroll
        for (int w = 0; w < 16; ++w) s += wacc[w];
        atomicAdd(out, -s);
    }
}

// ============================ launch ============================
extern "C" void kernel_launch(void* const* d_in, const int* in_sizes, int n_in,
                              void* d_out, int out_size) {
    const float* adj = (const float*)d_in[0];
    const float* X   = (const float*)d_in[1];
    float* out = (float*)d_out;

    cudaFuncSetAttribute(k3_tri, cudaFuncAttributeMaxDynamicSharedMemorySize,
                         K3_SMEM);

    k0_zero<<<32, 256>>>(out);
    k1_sums<<<148, 256>>>(adj);
    k2_prep<<<1024, 256>>>(X, out);
    k3_tri<<<148, 512, K3_SMEM>>>(adj, out);
}